// round 6
// baseline (speedup 1.0000x reference)
#include <cuda_runtime.h>
#include <cuda_bf16.h>
#include <math.h>
#include <cstdint>

// Problem constants
#define BATCH 4
#define C 128
#define NG 8
#define CPG 16
#define NTOK 4096
#define EPS 1e-5f
#define QSCALE (0.08838834764831845f * 1.4426950408889634f)  // 1/sqrt(C) * log2(e)

// Scratch
__device__ float         g_stats[BATCH * NG * 2];             // mean, rstd
__device__ __nv_bfloat16 g_qkv[BATCH * NTOK * 3 * C];         // [m][384] (q pre-scaled)

// ---------------------------------------------------------------------------
// helpers
// ---------------------------------------------------------------------------
__device__ __forceinline__ void mma_bf16(float* d, const uint32_t* a,
                                         uint32_t b0, uint32_t b1) {
    asm volatile(
        "mma.sync.aligned.m16n8k16.row.col.f32.bf16.bf16.f32 "
        "{%0,%1,%2,%3}, {%4,%5,%6,%7}, {%8,%9}, {%0,%1,%2,%3};"
        : "+f"(d[0]), "+f"(d[1]), "+f"(d[2]), "+f"(d[3])
        : "r"(a[0]), "r"(a[1]), "r"(a[2]), "r"(a[3]), "r"(b0), "r"(b1));
}
#define LDSM4(R, A) \
    asm volatile("ldmatrix.sync.aligned.m8n8.x4.shared.b16 {%0,%1,%2,%3}, [%4];" \
        : "=r"((R)[0]), "=r"((R)[1]), "=r"((R)[2]), "=r"((R)[3]) : "r"(A))
#define LDSM4T(R, A) \
    asm volatile("ldmatrix.sync.aligned.m8n8.x4.trans.shared.b16 {%0,%1,%2,%3}, [%4];" \
        : "=r"((R)[0]), "=r"((R)[1]), "=r"((R)[2]), "=r"((R)[3]) : "r"(A))
__device__ __forceinline__ void cp16(uint32_t dst, const void* src) {
    asm volatile("cp.async.ca.shared.global [%0], [%1], 16;" :: "r"(dst), "l"(src));
}
#define CP_COMMIT() asm volatile("cp.async.commit_group;" ::: "memory")
#define CP_WAIT(n)  asm volatile("cp.async.wait_group %0;" :: "n"(n) : "memory")
__device__ __forceinline__ uint32_t pack_bf2(float a, float b) {
    __nv_bfloat162 h = __floats2bfloat162_rn(a, b);
    return *reinterpret_cast<uint32_t*>(&h);
}
__device__ __forceinline__ float ex2f(float x) {
    float r;
    asm("ex2.approx.f32 %0, %1;" : "=f"(r) : "f"(x));
    return r;
}

// ---------------------------------------------------------------------------
// Kernel 1: GroupNorm statistics only. Grid 32 = (b, g). 256 threads.
// ---------------------------------------------------------------------------
__global__ void gn_stats_kernel(const float* __restrict__ x)
{
    int bg = blockIdx.x;
    const float4* xp = (const float4*)(x + (size_t)bg * CPG * NTOK);
    int t = threadIdx.x;

    float s = 0.f, ss = 0.f;
    for (int i = t; i < CPG * NTOK / 4; i += 256) {
        float4 v = xp[i];
        s  += v.x + v.y + v.z + v.w;
        ss += v.x * v.x + v.y * v.y + v.z * v.z + v.w * v.w;
    }
    __shared__ float red[512];
    red[t] = s; red[256 + t] = ss;
    __syncthreads();
    for (int o = 128; o > 0; o >>= 1) {
        if (t < o) { red[t] += red[t + o]; red[256 + t] += red[256 + t + o]; }
        __syncthreads();
    }
    if (t == 0) {
        float mean = red[0] * (1.f / (CPG * NTOK));
        float var  = red[256] * (1.f / (CPG * NTOK)) - mean * mean;
        g_stats[bg * 2]     = mean;
        g_stats[bg * 2 + 1] = rsqrtf(var + EPS);
    }
}

// ---------------------------------------------------------------------------
// Kernel 2: fused GroupNorm-normalize + QKV GEMM, bf16 HMMA.
// CTA: 128 tokens x all 384 outputs (3 o-blocks sequentially). Grid 128.
// A stored c-major [c][m] (ldmatrix.trans A-frags); B [o][c].
// ---------------------------------------------------------------------------
#define GP 136
#define QKV_SMEM ((128 * GP + 384 * GP) * 2)   // 139264 B

__global__ __launch_bounds__(256, 1) void qkv_kernel(const float* __restrict__ x,
                                                     const float* __restrict__ gnw,
                                                     const float* __restrict__ gnb,
                                                     const float* __restrict__ W,
                                                     const float* __restrict__ bias)
{
    extern __shared__ __nv_bfloat16 sq[];
    __nv_bfloat16* As = sq;              // [c][m] pitch GP
    __nv_bfloat16* Bs = sq + 128 * GP;   // [o][c] pitch GP
    const uint32_t sbase = (uint32_t)__cvta_generic_to_shared(sq);
    const int tid = threadIdx.x;
    const int w = tid >> 5, lane = tid & 31;
    const int gid = lane >> 2, tig = lane & 3;
    const int m0 = blockIdx.x * 128;
    const int b = m0 >> 12, n0 = m0 & 4095;

    // A: read x coalesced along n, normalize, store c-major
    for (int i = tid; i < 128 * 32; i += 256) {
        int c = i >> 5, n4 = (i & 31) << 2;
        float4 v = *(const float4*)(x + ((size_t)b * C + c) * NTOK + n0 + n4);
        int g = c >> 4;
        float mean = g_stats[(b * NG + g) * 2];
        float rstd = g_stats[(b * NG + g) * 2 + 1];
        float a = rstd * gnw[c];
        float bb = gnb[c] - mean * a;
        *(uint32_t*)(As + c * GP + n4)     = pack_bf2(v.x * a + bb, v.y * a + bb);
        *(uint32_t*)(As + c * GP + n4 + 2) = pack_bf2(v.z * a + bb, v.w * a + bb);
    }
    // B: all 384 weight rows
    for (int i = tid; i < 384 * 32; i += 256) {
        int r = i >> 5, c4 = (i & 31) << 2;
        float4 v = *(const float4*)(W + (size_t)r * C + c4);
        *(uint32_t*)(Bs + r * GP + c4)     = pack_bf2(v.x, v.y);
        *(uint32_t*)(Bs + r * GP + c4 + 2) = pack_bf2(v.z, v.w);
    }
    __syncthreads();

    const int l15 = lane & 15;
    const int hi8 = (lane >> 4) << 3;
    const int arow = (lane & 7) + ((lane >> 4) << 3);   // trans A-frag: bit4->row+8
    const int acol = ((lane >> 3) & 1) << 3;            //               bit3->col+8
    const uint32_t aA = sbase + (arow * GP + w * 16 + acol) * 2;
    const int mr = m0 + w * 16 + gid;

    for (int ob = 0; ob < 3; ob++) {
        const uint32_t aB = sbase + ((128 + ob * 128) * GP + l15 * GP + hi8) * 2;
        float acc[16][4];
#pragma unroll
        for (int i = 0; i < 16; i++)
#pragma unroll
            for (int j = 0; j < 4; j++) acc[i][j] = 0.f;

#pragma unroll
        for (int kk = 0; kk < 8; kk++) {
            const int k0 = kk * 16;
            uint32_t aq[4];
            LDSM4T(aq, aA + k0 * GP * 2);
#pragma unroll
            for (int ntp = 0; ntp < 8; ntp++) {
                uint32_t bk[4];
                LDSM4(bk, aB + (ntp * 16 * GP + k0) * 2);
                mma_bf16(acc[2 * ntp],     aq, bk[0], bk[2]);
                mma_bf16(acc[2 * ntp + 1], aq, bk[1], bk[3]);
            }
        }

        const float sc = (ob == 0) ? QSCALE : 1.f;
#pragma unroll
        for (int nt = 0; nt < 16; nt++) {
            int o = ob * 128 + nt * 8 + 2 * tig;
            float b0 = bias[o], b1 = bias[o + 1];
            *(uint32_t*)(g_qkv + (size_t)mr * 384 + o) =
                pack_bf2((acc[nt][0] + b0) * sc, (acc[nt][1] + b1) * sc);
            *(uint32_t*)(g_qkv + (size_t)(mr + 8) * 384 + o) =
                pack_bf2((acc[nt][2] + b0) * sc, (acc[nt][3] + b1) * sc);
        }
    }
}

// ---------------------------------------------------------------------------
// Kernel 3: flash attention (bf16 HMMA, 3-stage cp.async K/V, register P)
//           + fused proj + bias + residual epilogue.
// CTA = (q-tile 128, batch). 8 warps.
// ---------------------------------------------------------------------------
#define TQ 128
#define TKEY 64
#define QP 136
#define KS_OFF (TQ * QP)                   // Q: 17408 elems
#define STAGE (2 * TKEY * QP)              // K+V per stage: 17408 elems
#define VS_REL (TKEY * QP)
#define WS_OFF (KS_OFF + 3 * STAGE)        // 69632 elems
#define ATTN_SMEM ((WS_OFF + 128 * GP) * 2)  // 174080 B

__global__ __launch_bounds__(256, 1) void attn_kernel(const float* __restrict__ pw,
                                                      const float* __restrict__ pb,
                                                      const float* __restrict__ x,
                                                      float* __restrict__ y)
{
    extern __shared__ __nv_bfloat16 sb[];
    const uint32_t sbase = (uint32_t)__cvta_generic_to_shared(sb);
    const int tid = threadIdx.x;
    const int w = tid >> 5, lane = tid & 31;
    const int gid = lane >> 2, tig = lane & 3;
    const int qrow = w * 16 + gid;
    const int b = blockIdx.y;
    const int n0 = blockIdx.x * TQ;
    const __nv_bfloat16* Qb = g_qkv + (size_t)b * NTOK * 384;

    auto issueKV = [&](int jt, int s) {
        const int j0 = jt * TKEY;
        const uint32_t base = sbase + (KS_OFF + s * STAGE) * 2;
#pragma unroll
        for (int it = 0; it < 8; it++) {
            int i = tid + it * 256;
            int kv = i >> 10;
            int r = (i >> 4) & 63;
            int c8 = (i & 15) << 3;
            cp16(base + (kv * VS_REL + r * QP + c8) * 2,
                 Qb + (size_t)(j0 + r) * 384 + 128 + (kv << 7) + c8);
        }
    };

    issueKV(0, 0); CP_COMMIT();
    issueKV(1, 1); CP_COMMIT();

    // Q tile + W_proj (convert fp32->bf16), overlapped with cp.async
    for (int i = tid; i < TQ * 16; i += 256) {
        int r = i >> 4, c8 = (i & 15) << 3;
        *(uint4*)(sb + r * QP + c8) = *(const uint4*)(Qb + (size_t)(n0 + r) * 384 + c8);
    }
    for (int i = tid; i < 128 * 32; i += 256) {
        int r = i >> 5, c4 = (i & 31) << 2;
        float4 v = *(const float4*)(pw + (size_t)r * C + c4);
        *(uint32_t*)(sb + WS_OFF + r * GP + c4)     = pack_bf2(v.x, v.y);
        *(uint32_t*)(sb + WS_OFF + r * GP + c4 + 2) = pack_bf2(v.z, v.w);
    }

    const int l15 = lane & 15;
    const int hi8 = (lane >> 4) << 3;
    const uint32_t aQ = sbase + ((w * 16 + l15) * QP + hi8) * 2;
    const int vrow = (lane & 7) + ((lane >> 3) & 1) * 8;

    float oacc[16][4];
#pragma unroll
    for (int i = 0; i < 16; i++)
#pragma unroll
        for (int j = 0; j < 4; j++) oacc[i][j] = 0.f;
    float l0 = 0.f, l1 = 0.f;

    const int NT = NTOK / TKEY;
    for (int jt = 0; jt < NT; jt++) {
        const int s = jt % 3;
        if (jt + 2 < NT) {
            issueKV(jt + 2, (jt + 2) % 3);
            CP_COMMIT();
            CP_WAIT(2);
        } else if (jt + 1 < NT) {
            CP_WAIT(1);
        } else {
            CP_WAIT(0);
        }
        __syncthreads();

        const uint32_t aK = sbase + (KS_OFF + s * STAGE + l15 * QP + hi8) * 2;
        const uint32_t aV = sbase + (KS_OFF + s * STAGE + VS_REL + vrow * QP + hi8) * 2;

        // ---- S = Q K^T (logits already in log2 units) ----
        float sacc[8][4];
#pragma unroll
        for (int i = 0; i < 8; i++)
#pragma unroll
            for (int j = 0; j < 4; j++) sacc[i][j] = 0.f;

#pragma unroll
        for (int kk = 0; kk < 8; kk++) {
            const int k0 = kk * 16;
            uint32_t aq[4];
            LDSM4(aq, aQ + k0 * 2);
#pragma unroll
            for (int ntp = 0; ntp < 4; ntp++) {
                uint32_t bk[4];
                LDSM4(bk, aK + (ntp * 16 * QP + k0) * 2);
                mma_bf16(sacc[2 * ntp],     aq, bk[0], bk[2]);
                mma_bf16(sacc[2 * ntp + 1], aq, bk[1], bk[3]);
            }
        }

        // ---- softmax in registers (ex2), pack P fragments ----
        uint32_t pr[8][2];
#pragma unroll
        for (int nt = 0; nt < 8; nt++) {
            float p0 = ex2f(sacc[nt][0]);
            float p1 = ex2f(sacc[nt][1]);
            float p2 = ex2f(sacc[nt][2]);
            float p3 = ex2f(sacc[nt][3]);
            l0 += p0 + p1;
            l1 += p2 + p3;
            pr[nt][0] = pack_bf2(p0, p1);
            pr[nt][1] = pack_bf2(p2, p3);
        }

        // ---- O += P V ----
#pragma unroll
        for (int kk = 0; kk < 4; kk++) {
            const int k0 = kk * 16;
            uint32_t ap[4] = {pr[2 * kk][0], pr[2 * kk][1],
                              pr[2 * kk + 1][0], pr[2 * kk + 1][1]};
#pragma unroll
            for (int ccp = 0; ccp < 8; ccp++) {
                uint32_t bv[4];
                LDSM4T(bv, aV + (k0 * QP + ccp * 16) * 2);
                mma_bf16(oacc[2 * ccp],     ap, bv[0], bv[1]);
                mma_bf16(oacc[2 * ccp + 1], ap, bv[2], bv[3]);
            }
        }
        __syncthreads();
    }

    // ---- finalize O, write bf16 into retired stage smem ----
    l0 += __shfl_xor_sync(0xffffffffu, l0, 1);
    l0 += __shfl_xor_sync(0xffffffffu, l0, 2);
    l1 += __shfl_xor_sync(0xffffffffu, l1, 1);
    l1 += __shfl_xor_sync(0xffffffffu, l1, 2);
    float inv0 = 1.f / l0, inv1 = 1.f / l1;

    __nv_bfloat16* Os = sb + KS_OFF;     // [m][c] pitch GP
#pragma unroll
    for (int nt = 0; nt < 16; nt++) {
        int col = nt * 8 + 2 * tig;
        *(uint32_t*)(Os + qrow * GP + col) =
            pack_bf2(oacc[nt][0] * inv0, oacc[nt][1] * inv0);
        *(uint32_t*)(Os + (qrow + 8) * GP + col) =
            pack_bf2(oacc[nt][2] * inv1, oacc[nt][3] * inv1);
    }
    __syncthreads();

    // ---- fused proj: y = x + O @ Wp^T + pb ----
    const uint32_t aO = sbase + (KS_OFF + (w * 16 + l15) * QP + hi8) * 2;
    const uint32_t aW = sbase + (WS_OFF + l15 * GP + hi8) * 2;

    float acc[16][4];
#pragma unroll
    for (int i = 0; i < 16; i++)
#pragma unroll
        for (int j = 0; j < 4; j++) acc[i][j] = 0.f;

#pragma unroll
    for (int kk = 0; kk < 8; kk++) {
        const int k0 = kk * 16;
        uint32_t aq[4];
        LDSM4(aq, aO + k0 * 2);
#pragma unroll
        for (int ntp = 0; ntp < 8; ntp++) {
            uint32_t bk[4];
            LDSM4(bk, aW + (ntp * 16 * GP + k0) * 2);
            mma_bf16(acc[2 * ntp],     aq, bk[0], bk[2]);
            mma_bf16(acc[2 * ntp + 1], aq, bk[1], bk[3]);
        }
    }

    const int n = n0 + w * 16 + gid;
#pragma unroll
    for (int nt = 0; nt < 16; nt++) {
        int o = nt * 8 + 2 * tig;
        float b0 = pb[o], b1 = pb[o + 1];
        size_t a0 = ((size_t)b * C + o) * NTOK + n;
        size_t a1 = a0 + NTOK;
        y[a0]     = x[a0]     + acc[nt][0] + b0;
        y[a1]     = x[a1]     + acc[nt][1] + b1;
        y[a0 + 8] = x[a0 + 8] + acc[nt][2] + b0;
        y[a1 + 8] = x[a1 + 8] + acc[nt][3] + b1;
    }
}

// ---------------------------------------------------------------------------
extern "C" void kernel_launch(void* const* d_in, const int* in_sizes, int n_in,
                              void* d_out, int out_size)
{
    const float* x     = (const float*)d_in[0];
    const float* gn_w  = (const float*)d_in[1];
    const float* gn_b  = (const float*)d_in[2];
    const float* qkv_w = (const float*)d_in[3];
    const float* qkv_b = (const float*)d_in[4];
    const float* pr_w  = (const float*)d_in[5];
    const float* pr_b  = (const float*)d_in[6];
    float* y = (float*)d_out;

    cudaFuncSetAttribute(qkv_kernel,  cudaFuncAttributeMaxDynamicSharedMemorySize, QKV_SMEM);
    cudaFuncSetAttribute(attn_kernel, cudaFuncAttributeMaxDynamicSharedMemorySize, ATTN_SMEM);

    gn_stats_kernel<<<BATCH * NG, 256>>>(x);
    qkv_kernel<<<(BATCH * NTOK) / 128, 256, QKV_SMEM>>>(x, gn_w, gn_b, qkv_w, qkv_b);
    attn_kernel<<<dim3(NTOK / TQ, BATCH), 256, ATTN_SMEM>>>(pr_w, pr_b, x, y);
}

// round 7
// speedup vs baseline: 1.5436x; 1.5436x over previous
#include <cuda_runtime.h>
#include <cuda_bf16.h>
#include <math.h>
#include <cstdint>

// Problem constants
#define BATCH 4
#define C 128
#define NG 8
#define CPG 16
#define NTOK 4096
#define EPS 1e-5f
#define QSCALE (0.08838834764831845f * 1.4426950408889634f)  // 1/sqrt(C) * log2(e)

// Scratch
__device__ float2        g_part[BATCH * NG * 8];              // partial (sum, sumsq)
__device__ __nv_bfloat16 g_qkv[BATCH * NTOK * 3 * C];         // [m][384] (q pre-scaled)

// ---------------------------------------------------------------------------
// helpers
// ---------------------------------------------------------------------------
__device__ __forceinline__ void mma_bf16(float* d, const uint32_t* a,
                                         uint32_t b0, uint32_t b1) {
    asm volatile(
        "mma.sync.aligned.m16n8k16.row.col.f32.bf16.bf16.f32 "
        "{%0,%1,%2,%3}, {%4,%5,%6,%7}, {%8,%9}, {%0,%1,%2,%3};"
        : "+f"(d[0]), "+f"(d[1]), "+f"(d[2]), "+f"(d[3])
        : "r"(a[0]), "r"(a[1]), "r"(a[2]), "r"(a[3]), "r"(b0), "r"(b1));
}
#define LDSM4(R, A) \
    asm volatile("ldmatrix.sync.aligned.m8n8.x4.shared.b16 {%0,%1,%2,%3}, [%4];" \
        : "=r"((R)[0]), "=r"((R)[1]), "=r"((R)[2]), "=r"((R)[3]) : "r"(A))
#define LDSM4T(R, A) \
    asm volatile("ldmatrix.sync.aligned.m8n8.x4.trans.shared.b16 {%0,%1,%2,%3}, [%4];" \
        : "=r"((R)[0]), "=r"((R)[1]), "=r"((R)[2]), "=r"((R)[3]) : "r"(A))
__device__ __forceinline__ void cp16(uint32_t dst, const void* src) {
    asm volatile("cp.async.ca.shared.global [%0], [%1], 16;" :: "r"(dst), "l"(src));
}
#define CP_COMMIT() asm volatile("cp.async.commit_group;" ::: "memory")
#define CP_WAIT(n)  asm volatile("cp.async.wait_group %0;" :: "n"(n) : "memory")
__device__ __forceinline__ uint32_t pack_bf2(float a, float b) {
    __nv_bfloat162 h = __floats2bfloat162_rn(a, b);
    return *reinterpret_cast<uint32_t*>(&h);
}
__device__ __forceinline__ float ex2f(float x) {
    float r;
    asm("ex2.approx.f32 %0, %1;" : "=f"(r) : "f"(x));
    return r;
}

// ---------------------------------------------------------------------------
// Kernel 1: GroupNorm partial stats. Grid 256 = (bg 32) x (chunk 8).
// Each CTA sums 8192 floats (32 KB). Deterministic tree reduction.
// ---------------------------------------------------------------------------
__global__ void gn_stats_kernel(const float* __restrict__ x)
{
    int bg = blockIdx.x >> 3, ck = blockIdx.x & 7;
    const float4* xp = (const float4*)(x + (size_t)bg * CPG * NTOK
                                         + (size_t)ck * (CPG * NTOK / 8));
    int t = threadIdx.x;
    float s = 0.f, ss = 0.f;
#pragma unroll
    for (int i = 0; i < 8; i++) {
        float4 v = xp[t + i * 256];
        s  += v.x + v.y + v.z + v.w;
        ss += v.x * v.x + v.y * v.y + v.z * v.z + v.w * v.w;
    }
#pragma unroll
    for (int o = 16; o > 0; o >>= 1) {
        s  += __shfl_xor_sync(0xffffffffu, s, o);
        ss += __shfl_xor_sync(0xffffffffu, ss, o);
    }
    __shared__ float rs[8], rss[8];
    if ((t & 31) == 0) { rs[t >> 5] = s; rss[t >> 5] = ss; }
    __syncthreads();
    if (t == 0) {
        float a = 0.f, b = 0.f;
#pragma unroll
        for (int i = 0; i < 8; i++) { a += rs[i]; b += rss[i]; }
        g_part[blockIdx.x] = make_float2(a, b);
    }
}

// ---------------------------------------------------------------------------
// Kernel 2: fused GroupNorm-normalize + QKV GEMM, bf16 HMMA.
// Grid (128 m-tiles, 3 o-blocks). CTA: 128m x 128o x K=128, 69.6 KB smem.
// A stored c-major [c][m] (trans A-frags); B [o][c].
// ---------------------------------------------------------------------------
#define GP 136
#define QKV_SMEM (2 * 128 * GP * 2)    // 69632 B

__global__ __launch_bounds__(256, 1) void qkv_kernel(const float* __restrict__ x,
                                                     const float* __restrict__ gnw,
                                                     const float* __restrict__ gnb,
                                                     const float* __restrict__ W,
                                                     const float* __restrict__ bias)
{
    extern __shared__ __nv_bfloat16 sq[];
    __nv_bfloat16* As = sq;              // [c][m] pitch GP
    __nv_bfloat16* Bs = sq + 128 * GP;   // [o][c] pitch GP
    const uint32_t sbase = (uint32_t)__cvta_generic_to_shared(sq);
    const int tid = threadIdx.x;
    const int w = tid >> 5, lane = tid & 31;
    const int gid = lane >> 2, tig = lane & 3;
    const int m0 = blockIdx.x * 128, o0 = blockIdx.y * 128;
    const int b = m0 >> 12, n0 = m0 & 4095;

    // finalize group stats for this batch (8 threads, deterministic)
    __shared__ float stats[16];
    if (tid < 8) {
        float s = 0.f, ss = 0.f;
#pragma unroll
        for (int ck = 0; ck < 8; ck++) {
            float2 p = g_part[(b * NG + tid) * 8 + ck];
            s += p.x; ss += p.y;
        }
        float mean = s * (1.f / (CPG * NTOK));
        float var  = ss * (1.f / (CPG * NTOK)) - mean * mean;
        stats[tid * 2]     = mean;
        stats[tid * 2 + 1] = rsqrtf(var + EPS);
    }
    __syncthreads();

    // A: read x coalesced along n, normalize, store c-major
    for (int i = tid; i < 128 * 32; i += 256) {
        int c = i >> 5, n4 = (i & 31) << 2;
        float4 v = *(const float4*)(x + ((size_t)b * C + c) * NTOK + n0 + n4);
        int g = c >> 4;
        float a = stats[g * 2 + 1] * gnw[c];
        float bb = gnb[c] - stats[g * 2] * a;
        *(uint32_t*)(As + c * GP + n4)     = pack_bf2(v.x * a + bb, v.y * a + bb);
        *(uint32_t*)(As + c * GP + n4 + 2) = pack_bf2(v.z * a + bb, v.w * a + bb);
    }
    // B: this o-block's 128 weight rows
    for (int i = tid; i < 128 * 32; i += 256) {
        int r = i >> 5, c4 = (i & 31) << 2;
        float4 v = *(const float4*)(W + (size_t)(o0 + r) * C + c4);
        *(uint32_t*)(Bs + r * GP + c4)     = pack_bf2(v.x, v.y);
        *(uint32_t*)(Bs + r * GP + c4 + 2) = pack_bf2(v.z, v.w);
    }
    __syncthreads();

    const int l15 = lane & 15;
    const int hi8 = (lane >> 4) << 3;
    const int arow = (lane & 7) + ((lane >> 4) << 3);
    const int acol = ((lane >> 3) & 1) << 3;
    const uint32_t aA = sbase + (arow * GP + w * 16 + acol) * 2;
    const uint32_t aB = sbase + (128 * GP + l15 * GP + hi8) * 2;

    float acc[16][4];
#pragma unroll
    for (int i = 0; i < 16; i++)
#pragma unroll
        for (int j = 0; j < 4; j++) acc[i][j] = 0.f;

#pragma unroll
    for (int kk = 0; kk < 8; kk++) {
        const int k0 = kk * 16;
        uint32_t aq[4];
        LDSM4T(aq, aA + k0 * GP * 2);
#pragma unroll
        for (int ntp = 0; ntp < 8; ntp++) {
            uint32_t bk[4];
            LDSM4(bk, aB + (ntp * 16 * GP + k0) * 2);
            mma_bf16(acc[2 * ntp],     aq, bk[0], bk[2]);
            mma_bf16(acc[2 * ntp + 1], aq, bk[1], bk[3]);
        }
    }

    const float sc = (o0 == 0) ? QSCALE : 1.f;
    const int mr = m0 + w * 16 + gid;
#pragma unroll
    for (int nt = 0; nt < 16; nt++) {
        int o = o0 + nt * 8 + 2 * tig;
        float b0 = bias[o], b1 = bias[o + 1];
        *(uint32_t*)(g_qkv + (size_t)mr * 384 + o) =
            pack_bf2((acc[nt][0] + b0) * sc, (acc[nt][1] + b1) * sc);
        *(uint32_t*)(g_qkv + (size_t)(mr + 8) * 384 + o) =
            pack_bf2((acc[nt][2] + b0) * sc, (acc[nt][3] + b1) * sc);
    }
}

// ---------------------------------------------------------------------------
// Kernel 3: flash attention (bf16 HMMA, 2-stage cp.async K/V, register P)
//           + fused proj + bias + residual epilogue. O reuses Q smem region.
// CTA = (q-tile 128, batch). 8 warps.
// ---------------------------------------------------------------------------
#define TQ 128
#define TKEY 64
#define QP 136
#define KS_OFF (TQ * QP)                   // Q region: 17408 elems
#define STAGE (2 * TKEY * QP)              // K+V per stage: 17408 elems
#define VS_REL (TKEY * QP)
#define WS_OFF (KS_OFF + 2 * STAGE)        // 52224 elems
#define ATTN_SMEM ((WS_OFF + 128 * GP) * 2)  // 139264 B

__global__ __launch_bounds__(256, 1) void attn_kernel(const float* __restrict__ pw,
                                                      const float* __restrict__ pb,
                                                      const float* __restrict__ x,
                                                      float* __restrict__ y)
{
    extern __shared__ __nv_bfloat16 sb[];
    const uint32_t sbase = (uint32_t)__cvta_generic_to_shared(sb);
    const int tid = threadIdx.x;
    const int w = tid >> 5, lane = tid & 31;
    const int gid = lane >> 2, tig = lane & 3;
    const int qrow = w * 16 + gid;
    const int b = blockIdx.y;
    const int n0 = blockIdx.x * TQ;
    const __nv_bfloat16* Qb = g_qkv + (size_t)b * NTOK * 384;

    auto issueKV = [&](int jt, int s) {
        const int j0 = jt * TKEY;
        const uint32_t base = sbase + (KS_OFF + s * STAGE) * 2;
#pragma unroll
        for (int it = 0; it < 8; it++) {
            int i = tid + it * 256;
            int kv = i >> 10;
            int r = (i >> 4) & 63;
            int c8 = (i & 15) << 3;
            cp16(base + (kv * VS_REL + r * QP + c8) * 2,
                 Qb + (size_t)(j0 + r) * 384 + 128 + (kv << 7) + c8);
        }
    };

    issueKV(0, 0);
    CP_COMMIT();

    // Q tile + W_proj (fp32->bf16), overlapped with cp.async
    for (int i = tid; i < TQ * 16; i += 256) {
        int r = i >> 4, c8 = (i & 15) << 3;
        *(uint4*)(sb + r * QP + c8) = *(const uint4*)(Qb + (size_t)(n0 + r) * 384 + c8);
    }
    for (int i = tid; i < 128 * 32; i += 256) {
        int r = i >> 5, c4 = (i & 31) << 2;
        float4 v = *(const float4*)(pw + (size_t)r * C + c4);
        *(uint32_t*)(sb + WS_OFF + r * GP + c4)     = pack_bf2(v.x, v.y);
        *(uint32_t*)(sb + WS_OFF + r * GP + c4 + 2) = pack_bf2(v.z, v.w);
    }

    const int l15 = lane & 15;
    const int hi8 = (lane >> 4) << 3;
    const uint32_t aQ = sbase + ((w * 16 + l15) * QP + hi8) * 2;
    const int vrow = (lane & 7) + ((lane >> 3) & 1) * 8;

    float oacc[16][4];
#pragma unroll
    for (int i = 0; i < 16; i++)
#pragma unroll
        for (int j = 0; j < 4; j++) oacc[i][j] = 0.f;
    float l0 = 0.f, l1 = 0.f;

    const int NT = NTOK / TKEY;
    for (int jt = 0; jt < NT; jt++) {
        const int s = jt & 1;
        if (jt + 1 < NT) {
            issueKV(jt + 1, s ^ 1);
            CP_COMMIT();
            CP_WAIT(1);
        } else {
            CP_WAIT(0);
        }
        __syncthreads();

        const uint32_t aK = sbase + (KS_OFF + s * STAGE + l15 * QP + hi8) * 2;
        const uint32_t aV = sbase + (KS_OFF + s * STAGE + VS_REL + vrow * QP + hi8) * 2;

        // ---- S = Q K^T (logits in log2 units) ----
        float sacc[8][4];
#pragma unroll
        for (int i = 0; i < 8; i++)
#pragma unroll
            for (int j = 0; j < 4; j++) sacc[i][j] = 0.f;

#pragma unroll
        for (int kk = 0; kk < 8; kk++) {
            const int k0 = kk * 16;
            uint32_t aq[4];
            LDSM4(aq, aQ + k0 * 2);
#pragma unroll
            for (int ntp = 0; ntp < 4; ntp++) {
                uint32_t bk[4];
                LDSM4(bk, aK + (ntp * 16 * QP + k0) * 2);
                mma_bf16(sacc[2 * ntp],     aq, bk[0], bk[2]);
                mma_bf16(sacc[2 * ntp + 1], aq, bk[1], bk[3]);
            }
        }

        // ---- softmax in registers (ex2), pack P fragments ----
        uint32_t pr[8][2];
#pragma unroll
        for (int nt = 0; nt < 8; nt++) {
            float p0 = ex2f(sacc[nt][0]);
            float p1 = ex2f(sacc[nt][1]);
            float p2 = ex2f(sacc[nt][2]);
            float p3 = ex2f(sacc[nt][3]);
            l0 += p0 + p1;
            l1 += p2 + p3;
            pr[nt][0] = pack_bf2(p0, p1);
            pr[nt][1] = pack_bf2(p2, p3);
        }

        // ---- O += P V ----
#pragma unroll
        for (int kk = 0; kk < 4; kk++) {
            const int k0 = kk * 16;
            uint32_t ap[4] = {pr[2 * kk][0], pr[2 * kk][1],
                              pr[2 * kk + 1][0], pr[2 * kk + 1][1]};
#pragma unroll
            for (int ccp = 0; ccp < 8; ccp++) {
                uint32_t bv[4];
                LDSM4T(bv, aV + (k0 * QP + ccp * 16) * 2);
                mma_bf16(oacc[2 * ccp],     ap, bv[0], bv[1]);
                mma_bf16(oacc[2 * ccp + 1], ap, bv[2], bv[3]);
            }
        }
        __syncthreads();
    }

    // ---- finalize O into retired Q smem region ----
    l0 += __shfl_xor_sync(0xffffffffu, l0, 1);
    l0 += __shfl_xor_sync(0xffffffffu, l0, 2);
    l1 += __shfl_xor_sync(0xffffffffu, l1, 1);
    l1 += __shfl_xor_sync(0xffffffffu, l1, 2);
    float inv0 = 1.f / l0, inv1 = 1.f / l1;

#pragma unroll
    for (int nt = 0; nt < 16; nt++) {
        int col = nt * 8 + 2 * tig;
        *(uint32_t*)(sb + qrow * QP + col) =
            pack_bf2(oacc[nt][0] * inv0, oacc[nt][1] * inv0);
        *(uint32_t*)(sb + (qrow + 8) * QP + col) =
            pack_bf2(oacc[nt][2] * inv1, oacc[nt][3] * inv1);
    }
    __syncthreads();

    // ---- fused proj: y = x + O @ Wp^T + pb ----
    const uint32_t aW = sbase + (WS_OFF + l15 * GP + hi8) * 2;

    float acc[16][4];
#pragma unroll
    for (int i = 0; i < 16; i++)
#pragma unroll
        for (int j = 0; j < 4; j++) acc[i][j] = 0.f;

#pragma unroll
    for (int kk = 0; kk < 8; kk++) {
        const int k0 = kk * 16;
        uint32_t aq[4];
        LDSM4(aq, aQ + k0 * 2);            // O lives in Q region, same frag addr
#pragma unroll
        for (int ntp = 0; ntp < 8; ntp++) {
            uint32_t bk[4];
            LDSM4(bk, aW + (ntp * 16 * GP + k0) * 2);
            mma_bf16(acc[2 * ntp],     aq, bk[0], bk[2]);
            mma_bf16(acc[2 * ntp + 1], aq, bk[1], bk[3]);
        }
    }

    const int n = n0 + w * 16 + gid;
#pragma unroll
    for (int nt = 0; nt < 16; nt++) {
        int o = nt * 8 + 2 * tig;
        float b0 = pb[o], b1 = pb[o + 1];
        size_t a0 = ((size_t)b * C + o) * NTOK + n;
        size_t a1 = a0 + NTOK;
        y[a0]     = x[a0]     + acc[nt][0] + b0;
        y[a1]     = x[a1]     + acc[nt][1] + b1;
        y[a0 + 8] = x[a0 + 8] + acc[nt][2] + b0;
        y[a1 + 8] = x[a1 + 8] + acc[nt][3] + b1;
    }
}

// ---------------------------------------------------------------------------
extern "C" void kernel_launch(void* const* d_in, const int* in_sizes, int n_in,
                              void* d_out, int out_size)
{
    const float* x     = (const float*)d_in[0];
    const float* gn_w  = (const float*)d_in[1];
    const float* gn_b  = (const float*)d_in[2];
    const float* qkv_w = (const float*)d_in[3];
    const float* qkv_b = (const float*)d_in[4];
    const float* pr_w  = (const float*)d_in[5];
    const float* pr_b  = (const float*)d_in[6];
    float* y = (float*)d_out;

    cudaFuncSetAttribute(qkv_kernel,  cudaFuncAttributeMaxDynamicSharedMemorySize, QKV_SMEM);
    cudaFuncSetAttribute(attn_kernel, cudaFuncAttributeMaxDynamicSharedMemorySize, ATTN_SMEM);

    gn_stats_kernel<<<BATCH * NG * 8, 256>>>(x);
    qkv_kernel<<<dim3((BATCH * NTOK) / 128, 3), 256, QKV_SMEM>>>(x, gn_w, gn_b, qkv_w, qkv_b);
    attn_kernel<<<dim3(NTOK / TQ, BATCH), 256, ATTN_SMEM>>>(pr_w, pr_b, x, y);
}